// round 5
// baseline (speedup 1.0000x reference)
#include <cuda_runtime.h>
#include <cuda_bf16.h>
#include <cstdint>
#include <math.h>

// ============================================================
// R5: Flash attention, per-element scale, mma.sync m16n8k16 bf16
// hi/lo 3-term compensation. K/V pre-converted once (device scratch).
// Warp-specialized: 8 math warps + 1 producer warp, mbarrier
// full/free pipeline (2 stages), ping-pong tile order to keep the
// tensor pipe fed during softmax.
// ============================================================

constexpr int kS = 2048, kD = 128, kBQ = 128, kBK = 64;
constexpr int kThreads = 288;               // 8 math warps + 1 producer warp
constexpr int kIters = kS / kBK;            // 32
constexpr int kQTiles = kS / kBQ;           // 16

constexpr int kKVStrideB = 272;             // 136 bf16/row (ldmatrix conflict-free)
constexpr int kKVTileB   = 64 * kKVStrideB; // 17408
constexpr int kBlobB     = 4 * kKVTileB;    // khi,klo,vhi,vlo = 69632
constexpr int kScStrideB = 272;             // 68 floats
constexpr int kScTileB   = 128 * kScStrideB;// 34816

constexpr int SM_SC  = 2 * kBlobB;          // 139264
constexpr int SM_MB  = SM_SC + 2 * kScTileB;// 208896 (mbarriers)
constexpr int kSmemBytes = SM_MB + 64;      // 208960

// K/V pre-converted padded tile images: [bh][kt][blob]
__device__ __align__(16) unsigned char g_kv[32u * 32u * (unsigned)kBlobB];

__device__ __forceinline__ uint32_t smem_u32(const void* p) {
    uint32_t a;
    asm("{ .reg .u64 t; cvta.to.shared.u64 t, %1; cvt.u32.u64 %0, t; }" : "=r"(a) : "l"(p));
    return a;
}
__device__ __forceinline__ void cp16(uint32_t dst, const void* src) {
    asm volatile("cp.async.cg.shared.global [%0], [%1], 16;" :: "r"(dst), "l"(src));
}
__device__ __forceinline__ void cp_commit() { asm volatile("cp.async.commit_group;" ::: "memory"); }
__device__ __forceinline__ void cp_wait0()  { asm volatile("cp.async.wait_group 0;" ::: "memory"); }

#define MBAR_INIT(a, n) asm volatile("mbarrier.init.shared.b64 [%0], %1;" :: "r"(a), "r"(n) : "memory")
#define MBAR_ARRIVE(a)  asm volatile("mbarrier.arrive.shared.b64 _, [%0];" :: "r"(a) : "memory")
#define MBAR_WAIT(a, ph) do {                                                          \
    uint32_t _m = (a), _p = (ph), _d;                                                  \
    asm volatile("{ .reg .pred p; mbarrier.try_wait.parity.acquire.cta.shared::cta.b64 p, [%1], %2; selp.b32 %0,1,0,p; }" \
        : "=r"(_d) : "r"(_m), "r"(_p) : "memory");                                     \
    if (!_d) { asm volatile(                                                           \
        "{ .reg .pred P1; WL%=: mbarrier.try_wait.parity.acquire.cta.shared::cta.b64 P1, [%0], %1, 0x989680;\n\t" \
        "@P1 bra.uni WD%=; bra.uni WL%=; WD%=: }" :: "r"(_m), "r"(_p) : "memory"); }   \
} while (0)

__device__ __forceinline__ void ldsm_x4(uint32_t& r0, uint32_t& r1, uint32_t& r2, uint32_t& r3,
                                        uint32_t addr) {
    asm volatile("ldmatrix.sync.aligned.m8n8.x4.shared.b16 {%0,%1,%2,%3}, [%4];"
        : "=r"(r0), "=r"(r1), "=r"(r2), "=r"(r3) : "r"(addr));
}
__device__ __forceinline__ void ldsm_x4_t(uint32_t& r0, uint32_t& r1, uint32_t& r2, uint32_t& r3,
                                          uint32_t addr) {
    asm volatile("ldmatrix.sync.aligned.m8n8.x4.trans.shared.b16 {%0,%1,%2,%3}, [%4];"
        : "=r"(r0), "=r"(r1), "=r"(r2), "=r"(r3) : "r"(addr));
}
__device__ __forceinline__ void mma_bf16(float* d, const uint32_t* a, uint32_t b0, uint32_t b1) {
    asm volatile("mma.sync.aligned.m16n8k16.row.col.f32.bf16.bf16.f32 "
        "{%0,%1,%2,%3}, {%4,%5,%6,%7}, {%8,%9}, {%0,%1,%2,%3};"
        : "+f"(d[0]), "+f"(d[1]), "+f"(d[2]), "+f"(d[3])
        : "r"(a[0]), "r"(a[1]), "r"(a[2]), "r"(a[3]), "r"(b0), "r"(b1));
}
__device__ __forceinline__ uint32_t packbf(float a, float b) {
    __nv_bfloat162 t = __floats2bfloat162_rn(a, b);
    return *reinterpret_cast<uint32_t*>(&t);
}
__device__ __forceinline__ void split2(float a, float b, uint32_t& hi, uint32_t& lo) {
    __nv_bfloat16 ah = __float2bfloat16(a), bh = __float2bfloat16(b);
    __nv_bfloat162 h; h.x = ah; h.y = bh;
    hi = *reinterpret_cast<uint32_t*>(&h);
    lo = packbf(a - __bfloat162float(ah), b - __bfloat162float(bh));
}
__device__ __forceinline__ float decode_scalar(const void* p) {
    const int w = *reinterpret_cast<const int*>(p);
    if (w > -(1 << 23) && w < (1 << 23)) return (float)w;
    return __int_as_float(w);
}

// ---------------- precompute: K,V -> bf16 hi/lo padded tile images ----------------
__global__ __launch_bounds__(256, 4)
void convert_kv_kernel(const float* __restrict__ k, const float* __restrict__ v) {
    const int kt = (int)blockIdx.x, bh = (int)blockIdx.y, tid = (int)threadIdx.x;
    unsigned char* blob = g_kv + (size_t)(bh * 32 + kt) * kBlobB;
    const float* kgt = k + ((size_t)bh * kS + (size_t)kt * kBK) * kD;
    const float* vgt = v + ((size_t)bh * kS + (size_t)kt * kBK) * kD;
    #pragma unroll
    for (int it = 0; it < 8; ++it) {
        const int idx = it * 256 + tid;
        const int r = idx >> 5, c = (idx & 31) << 2;
        const int so = r * kKVStrideB + c * 2;
        {
            const float4 x = reinterpret_cast<const float4*>(kgt)[idx];
            uint32_t h0, l0, h1, l1;
            split2(x.x, x.y, h0, l0);
            split2(x.z, x.w, h1, l1);
            *reinterpret_cast<uint2*>(blob + so)            = make_uint2(h0, h1);
            *reinterpret_cast<uint2*>(blob + kKVTileB + so) = make_uint2(l0, l1);
        }
        {
            const float4 x = reinterpret_cast<const float4*>(vgt)[idx];
            uint32_t h0, l0, h1, l1;
            split2(x.x, x.y, h0, l0);
            split2(x.z, x.w, h1, l1);
            *reinterpret_cast<uint2*>(blob + 2 * kKVTileB + so) = make_uint2(h0, h1);
            *reinterpret_cast<uint2*>(blob + 3 * kKVTileB + so) = make_uint2(l0, l1);
        }
    }
}

// ---------------- main kernel ----------------
__global__ __launch_bounds__(kThreads, 1)
void flash_mma_kernel(const float* __restrict__ q,
                      const float* __restrict__ sf,
                      const void*  __restrict__ dropout_p,
                      float* __restrict__ out) {
    extern __shared__ char smem[];
    const uint32_t sb = smem_u32(smem);
    const int tid  = (int)threadIdx.x;
    const int wid  = tid >> 5;
    const int lane = tid & 31;
    const int qt = (int)blockIdx.x;
    const int bh = (int)blockIdx.y;

    const float* sg = sf + (size_t)(qt * kBQ) * kS;

    const uint32_t mb_full0 = sb + SM_MB, mb_full1 = sb + SM_MB + 8;
    const uint32_t mb_free0 = sb + SM_MB + 16, mb_free1 = sb + SM_MB + 24;

    if (tid == 0) {
        MBAR_INIT(mb_full0, 32);  MBAR_INIT(mb_full1, 32);   // producer lanes arrive
        MBAR_INIT(mb_free0, 8);   MBAR_INIT(mb_free1, 8);    // one per math warp
    }
    __syncthreads();

    if (wid == 8) {
        // =============== producer warp ===============
        for (int kt = 0; kt < kIters; ++kt) {
            const int st = kt & 1;
            if (kt >= 2) MBAR_WAIT(st ? mb_free1 : mb_free0, ((kt >> 1) - 1) & 1);
            const unsigned char* src = g_kv + (size_t)(bh * 32 + kt) * kBlobB;
            const uint32_t dkv = sb + (uint32_t)st * kBlobB;
            #pragma unroll 8
            for (int i = 0; i < 136; ++i) {               // 4352 / 32 lanes
                const int op = i * 32 + lane;
                cp16(dkv + op * 16, src + (size_t)op * 16);
            }
            const unsigned char* ssc = reinterpret_cast<const unsigned char*>(sg + (size_t)kt * kBK);
            const uint32_t dsc = sb + SM_SC + (uint32_t)st * kScTileB;
            #pragma unroll 8
            for (int i = 0; i < 64; ++i) {                // 2048 / 32 lanes
                const int op = i * 32 + lane;
                const int r = op >> 4, c = op & 15;
                cp16(dsc + (uint32_t)(r * kScStrideB + c * 16),
                     ssc + (size_t)r * (kS * 4) + c * 16);
            }
            cp_commit();
            cp_wait0();
            MBAR_ARRIVE(st ? mb_full1 : mb_full0);        // all 32 lanes (count 32)
        }
        return;
    }

    // =============== math warps (0-7) ===============
    const int g  = lane >> 2;
    const int t  = lane & 3;
    const int w8 = lane & 7;
    const int b3 = (lane >> 3) & 1;
    const int b4 = (lane >> 4) & 1;
    const float* qg = q + ((size_t)bh * kS + (size_t)qt * kBQ) * kD;

    // Q fragments (hi/lo) in registers
    uint32_t qhi[8][4], qlo[8][4];
    {
        const float* rq0 = qg + (size_t)(wid * 16 + g) * kD;
        const float* rq8 = rq0 + 8 * kD;
        #pragma unroll
        for (int ks = 0; ks < 8; ++ks) {
            const int c = ks * 16 + 2 * t;
            const float2 f0 = *reinterpret_cast<const float2*>(rq0 + c);
            const float2 f1 = *reinterpret_cast<const float2*>(rq8 + c);
            const float2 f2 = *reinterpret_cast<const float2*>(rq0 + c + 8);
            const float2 f3 = *reinterpret_cast<const float2*>(rq8 + c + 8);
            split2(f0.x, f0.y, qhi[ks][0], qlo[ks][0]);
            split2(f1.x, f1.y, qhi[ks][1], qlo[ks][1]);
            split2(f2.x, f2.y, qhi[ks][2], qlo[ks][2]);
            split2(f3.x, f3.y, qhi[ks][3], qlo[ks][3]);
        }
    }

    float oacc[16][4];
    #pragma unroll
    for (int n = 0; n < 16; ++n)
        #pragma unroll
        for (int c = 0; c < 4; ++c) oacc[n][c] = 0.f;
    float m0 = -INFINITY, m1 = -INFINITY, l0 = 0.f, l1 = 0.f;
    const bool groupB = (wid >= 4);

    for (int j = 0; j < kIters; ++j) {
        const int kt = groupB ? (j ^ 1) : j;   // ping-pong tile order for group B
        const int st = kt & 1;
        MBAR_WAIT(st ? mb_full1 : mb_full0, (kt >> 1) & 1);

        const uint32_t KHI = sb + (uint32_t)st * kBlobB;
        const uint32_t KLO = KHI + kKVTileB;
        const uint32_t VHI = KHI + 2 * kKVTileB;
        const uint32_t VLO = KHI + 3 * kKVTileB;

        // ---- S = Q K^T (3-term) ----
        float sacc[8][4];
        #pragma unroll
        for (int n = 0; n < 8; ++n)
            #pragma unroll
            for (int c = 0; c < 4; ++c) sacc[n][c] = 0.f;

        #pragma unroll
        for (int ks = 0; ks < 8; ++ks) {
            #pragma unroll
            for (int h = 0; h < 2; ++h) {
                uint32_t bhi[4][2], blo[4][2];
                #pragma unroll
                for (int p = 0; p < 2; ++p) {
                    const int pg = h * 2 + p;
                    const uint32_t off = (uint32_t)((pg * 16 + b4 * 8 + w8) * kKVStrideB
                                                    + (ks * 16 + b3 * 8) * 2);
                    ldsm_x4(bhi[2*p][0], bhi[2*p][1], bhi[2*p+1][0], bhi[2*p+1][1], KHI + off);
                    ldsm_x4(blo[2*p][0], blo[2*p][1], blo[2*p+1][0], blo[2*p+1][1], KLO + off);
                }
                #pragma unroll
                for (int n = 0; n < 4; ++n) {
                    float* sa = sacc[h * 4 + n];
                    mma_bf16(sa, qhi[ks], bhi[n][0], bhi[n][1]);
                    mma_bf16(sa, qhi[ks], blo[n][0], blo[n][1]);
                    mma_bf16(sa, qlo[ks], bhi[n][0], bhi[n][1]);
                }
            }
        }

        // ---- scale + online softmax ----
        const int r0 = wid * 16 + g;
        const char* scb = smem + SM_SC + (size_t)st * kScTileB;
        const char* sc0 = scb + (size_t)r0 * kScStrideB + (size_t)(2 * t) * 4;
        const char* sc1 = sc0 + (size_t)8 * kScStrideB;
        float mx0 = -INFINITY, mx1 = -INFINITY;
        #pragma unroll
        for (int n = 0; n < 8; ++n) {
            const float2 s0 = *reinterpret_cast<const float2*>(sc0 + n * 32);
            const float2 s1 = *reinterpret_cast<const float2*>(sc1 + n * 32);
            sacc[n][0] *= s0.x; sacc[n][1] *= s0.y;
            sacc[n][2] *= s1.x; sacc[n][3] *= s1.y;
            mx0 = fmaxf(mx0, fmaxf(sacc[n][0], sacc[n][1]));
            mx1 = fmaxf(mx1, fmaxf(sacc[n][2], sacc[n][3]));
        }
        #pragma unroll
        for (int off = 1; off <= 2; off <<= 1) {
            mx0 = fmaxf(mx0, __shfl_xor_sync(0xffffffffu, mx0, off));
            mx1 = fmaxf(mx1, __shfl_xor_sync(0xffffffffu, mx1, off));
        }
        const float m0n = fmaxf(m0, mx0), m1n = fmaxf(m1, mx1);
        const float a0 = __expf(m0 - m0n), a1 = __expf(m1 - m1n);

        float sum0 = 0.f, sum1 = 0.f;
        #pragma unroll
        for (int n = 0; n < 8; ++n) {
            sacc[n][0] = __expf(sacc[n][0] - m0n);
            sacc[n][1] = __expf(sacc[n][1] - m0n);
            sacc[n][2] = __expf(sacc[n][2] - m1n);
            sacc[n][3] = __expf(sacc[n][3] - m1n);
            sum0 += sacc[n][0] + sacc[n][1];
            sum1 += sacc[n][2] + sacc[n][3];
        }
        #pragma unroll
        for (int off = 1; off <= 2; off <<= 1) {
            sum0 += __shfl_xor_sync(0xffffffffu, sum0, off);
            sum1 += __shfl_xor_sync(0xffffffffu, sum1, off);
        }
        l0 = l0 * a0 + sum0;  m0 = m0n;
        l1 = l1 * a1 + sum1;  m1 = m1n;

        #pragma unroll
        for (int n = 0; n < 16; ++n) {
            oacc[n][0] *= a0; oacc[n][1] *= a0;
            oacc[n][2] *= a1; oacc[n][3] *= a1;
        }

        // ---- repack P -> A-frags (hi/lo) ----
        uint32_t phi[4][4], plo[4][4];
        #pragma unroll
        for (int jj = 0; jj < 4; ++jj) {
            split2(sacc[2*jj][0],   sacc[2*jj][1],   phi[jj][0], plo[jj][0]);
            split2(sacc[2*jj][2],   sacc[2*jj][3],   phi[jj][1], plo[jj][1]);
            split2(sacc[2*jj+1][0], sacc[2*jj+1][1], phi[jj][2], plo[jj][2]);
            split2(sacc[2*jj+1][2], sacc[2*jj+1][3], phi[jj][3], plo[jj][3]);
        }

        // ---- O += P V ----
        #pragma unroll
        for (int jj = 0; jj < 4; ++jj) {
            #pragma unroll
            for (int pp = 0; pp < 8; ++pp) {
                const uint32_t off = (uint32_t)((jj * 16 + b3 * 8 + w8) * kKVStrideB
                                                + (pp * 16 + b4 * 8) * 2);
                uint32_t vh0, vh1, vh2, vh3, vl0, vl1, vl2, vl3;
                ldsm_x4_t(vh0, vh1, vh2, vh3, VHI + off);
                ldsm_x4_t(vl0, vl1, vl2, vl3, VLO + off);
                mma_bf16(oacc[2*pp],   phi[jj], vh0, vh1);
                mma_bf16(oacc[2*pp],   phi[jj], vl0, vl1);
                mma_bf16(oacc[2*pp],   plo[jj], vh0, vh1);
                mma_bf16(oacc[2*pp+1], phi[jj], vh2, vh3);
                mma_bf16(oacc[2*pp+1], phi[jj], vl2, vl3);
                mma_bf16(oacc[2*pp+1], plo[jj], vh2, vh3);
            }
        }

        __syncwarp();
        if (lane == 0) MBAR_ARRIVE(st ? mb_free1 : mb_free0);
    }

    // ---- epilogue ----
    const float dp = decode_scalar(dropout_p);
    const float inv0 = dp / l0, inv1 = dp / l1;
    const size_t row0 = (size_t)bh * kS + (size_t)qt * kBQ + (size_t)(wid * 16 + g);
    float* o0 = out + row0 * kD + 2 * t;
    float* o1 = o0 + (size_t)8 * kD;
    #pragma unroll
    for (int n = 0; n < 16; ++n) {
        *reinterpret_cast<float2*>(o0 + n * 8) = make_float2(oacc[n][0] * inv0, oacc[n][1] * inv0);
        *reinterpret_cast<float2*>(o1 + n * 8) = make_float2(oacc[n][2] * inv1, oacc[n][3] * inv1);
    }
}

extern "C" void kernel_launch(void* const* d_in, const int* in_sizes, int n_in,
                              void* d_out, int out_size) {
    const float* q  = (const float*)d_in[0];
    const float* k  = (const float*)d_in[1];
    const float* v  = (const float*)d_in[2];
    const float* sf = (const float*)d_in[3];
    const void*  dp = d_in[4];
    float* out = (float*)d_out;
    (void)in_sizes; (void)n_in; (void)out_size;

    dim3 cgrid(kIters, 32);
    convert_kv_kernel<<<cgrid, 256>>>(k, v);

    cudaFuncSetAttribute(flash_mma_kernel,
                         cudaFuncAttributeMaxDynamicSharedMemorySize, kSmemBytes);
    dim3 grid(kQTiles, 32);
    flash_mma_kernel<<<grid, kThreads, kSmemBytes>>>(q, sf, dp, out);
}

// round 7
// speedup vs baseline: 1.3150x; 1.3150x over previous
#include <cuda_runtime.h>
#include <cuda_bf16.h>
#include <cstdint>
#include <math.h>

// ============================================================
// R7: R4 structure (known good) + intra-warp interleave of
// softmax exp/repack with PV MMAs + scale tile read directly
// from gmem/L2 (removes SC smem traffic).
// Flash attention, per-element scale, mma.sync m16n8k16 bf16,
// hi/lo 3-term compensation, K/V pre-converted to padded tile
// images in device scratch, cp.async double-buffered.
// ============================================================

constexpr int kS = 2048, kD = 128, kBQ = 128, kBK = 64;
constexpr int kThreads = 256;
constexpr int kIters = kS / kBK;            // 32
constexpr int kQTiles = kS / kBQ;           // 16

constexpr int kKVStrideB = 272;             // 136 bf16/row (ldmatrix conflict-free)
constexpr int kKVTileB   = 64 * kKVStrideB; // 17408
constexpr int kBlobB     = 4 * kKVTileB;    // khi,klo,vhi,vlo = 69632
constexpr int kSmemBytes = 2 * kBlobB;      // 139264 (two stages)

// K/V pre-converted padded tile images: [bh][kt][blob]
__device__ __align__(16) unsigned char g_kv[32u * 32u * (unsigned)kBlobB];

__device__ __forceinline__ uint32_t smem_u32(const void* p) {
    uint32_t a;
    asm("{ .reg .u64 t; cvta.to.shared.u64 t, %1; cvt.u32.u64 %0, t; }" : "=r"(a) : "l"(p));
    return a;
}
__device__ __forceinline__ void cp16(uint32_t dst, const void* src) {
    asm volatile("cp.async.cg.shared.global [%0], [%1], 16;" :: "r"(dst), "l"(src));
}
__device__ __forceinline__ void cp_commit() { asm volatile("cp.async.commit_group;" ::: "memory"); }
__device__ __forceinline__ void cp_wait0()  { asm volatile("cp.async.wait_group 0;" ::: "memory"); }

__device__ __forceinline__ void ldsm_x4(uint32_t& r0, uint32_t& r1, uint32_t& r2, uint32_t& r3,
                                        uint32_t addr) {
    asm volatile("ldmatrix.sync.aligned.m8n8.x4.shared.b16 {%0,%1,%2,%3}, [%4];"
        : "=r"(r0), "=r"(r1), "=r"(r2), "=r"(r3) : "r"(addr));
}
__device__ __forceinline__ void ldsm_x4_t(uint32_t& r0, uint32_t& r1, uint32_t& r2, uint32_t& r3,
                                          uint32_t addr) {
    asm volatile("ldmatrix.sync.aligned.m8n8.x4.trans.shared.b16 {%0,%1,%2,%3}, [%4];"
        : "=r"(r0), "=r"(r1), "=r"(r2), "=r"(r3) : "r"(addr));
}
__device__ __forceinline__ void mma_bf16(float* d, const uint32_t* a, uint32_t b0, uint32_t b1) {
    asm volatile("mma.sync.aligned.m16n8k16.row.col.f32.bf16.bf16.f32 "
        "{%0,%1,%2,%3}, {%4,%5,%6,%7}, {%8,%9}, {%0,%1,%2,%3};"
        : "+f"(d[0]), "+f"(d[1]), "+f"(d[2]), "+f"(d[3])
        : "r"(a[0]), "r"(a[1]), "r"(a[2]), "r"(a[3]), "r"(b0), "r"(b1));
}
__device__ __forceinline__ uint32_t packbf(float a, float b) {
    __nv_bfloat162 t = __floats2bfloat162_rn(a, b);
    return *reinterpret_cast<uint32_t*>(&t);
}
__device__ __forceinline__ void split2(float a, float b, uint32_t& hi, uint32_t& lo) {
    __nv_bfloat16 ah = __float2bfloat16(a), bh = __float2bfloat16(b);
    __nv_bfloat162 h; h.x = ah; h.y = bh;
    hi = *reinterpret_cast<uint32_t*>(&h);
    lo = packbf(a - __bfloat162float(ah), b - __bfloat162float(bh));
}
__device__ __forceinline__ float decode_scalar(const void* p) {
    const int w = *reinterpret_cast<const int*>(p);
    if (w > -(1 << 23) && w < (1 << 23)) return (float)w;
    return __int_as_float(w);
}

// ---------------- precompute: K,V -> bf16 hi/lo padded tile images ----------------
__global__ __launch_bounds__(256, 4)
void convert_kv_kernel(const float* __restrict__ k, const float* __restrict__ v) {
    const int kt = (int)blockIdx.x, bh = (int)blockIdx.y, tid = (int)threadIdx.x;
    unsigned char* blob = g_kv + (size_t)(bh * 32 + kt) * kBlobB;
    const float* kgt = k + ((size_t)bh * kS + (size_t)kt * kBK) * kD;
    const float* vgt = v + ((size_t)bh * kS + (size_t)kt * kBK) * kD;
    #pragma unroll
    for (int it = 0; it < 8; ++it) {
        const int idx = it * 256 + tid;
        const int r = idx >> 5, c = (idx & 31) << 2;
        const int so = r * kKVStrideB + c * 2;
        {
            const float4 x = reinterpret_cast<const float4*>(kgt)[idx];
            uint32_t h0, l0, h1, l1;
            split2(x.x, x.y, h0, l0);
            split2(x.z, x.w, h1, l1);
            *reinterpret_cast<uint2*>(blob + so)            = make_uint2(h0, h1);
            *reinterpret_cast<uint2*>(blob + kKVTileB + so) = make_uint2(l0, l1);
        }
        {
            const float4 x = reinterpret_cast<const float4*>(vgt)[idx];
            uint32_t h0, l0, h1, l1;
            split2(x.x, x.y, h0, l0);
            split2(x.z, x.w, h1, l1);
            *reinterpret_cast<uint2*>(blob + 2 * kKVTileB + so) = make_uint2(h0, h1);
            *reinterpret_cast<uint2*>(blob + 3 * kKVTileB + so) = make_uint2(l0, l1);
        }
    }
}

// ---------------- main kernel ----------------
__global__ __launch_bounds__(kThreads, 1)
void flash_mma_kernel(const float* __restrict__ q,
                      const float* __restrict__ sf,
                      const void*  __restrict__ dropout_p,
                      float* __restrict__ out) {
    extern __shared__ char smem[];
    const uint32_t sb = smem_u32(smem);
    const int tid  = (int)threadIdx.x;
    const int wid  = tid >> 5;
    const int lane = tid & 31;
    const int g    = lane >> 2;
    const int t    = lane & 3;
    const int qt = (int)blockIdx.x;
    const int bh = (int)blockIdx.y;

    // KV blob copy, double buffered (same as R4, SC removed)
    auto issue_tile = [&](int kt, int stage) {
        const unsigned char* src = g_kv + (size_t)(bh * 32 + kt) * kBlobB;
        const uint32_t dkv = sb + (uint32_t)stage * kBlobB;
        #pragma unroll
        for (int i = 0; i < 17; ++i) {
            const int op = i * kThreads + tid;     // 4352 ops total
            cp16(dkv + op * 16, src + (size_t)op * 16);
        }
        cp_commit();
    };
    issue_tile(0, 0);

    // ---- Q fragments (hi/lo) in registers ----
    const float* qg = q + ((size_t)bh * kS + (size_t)qt * kBQ) * kD;
    uint32_t qhi[8][4], qlo[8][4];
    {
        const float* rq0 = qg + (size_t)(wid * 16 + g) * kD;
        const float* rq8 = rq0 + 8 * kD;
        #pragma unroll
        for (int ks = 0; ks < 8; ++ks) {
            const int c = ks * 16 + 2 * t;
            const float2 f0 = *reinterpret_cast<const float2*>(rq0 + c);
            const float2 f1 = *reinterpret_cast<const float2*>(rq8 + c);
            const float2 f2 = *reinterpret_cast<const float2*>(rq0 + c + 8);
            const float2 f3 = *reinterpret_cast<const float2*>(rq8 + c + 8);
            split2(f0.x, f0.y, qhi[ks][0], qlo[ks][0]);
            split2(f1.x, f1.y, qhi[ks][1], qlo[ks][1]);
            split2(f2.x, f2.y, qhi[ks][2], qlo[ks][2]);
            split2(f3.x, f3.y, qhi[ks][3], qlo[ks][3]);
        }
    }

    float oacc[16][4];
    #pragma unroll
    for (int n = 0; n < 16; ++n)
        #pragma unroll
        for (int c = 0; c < 4; ++c) oacc[n][c] = 0.f;
    float m0 = -INFINITY, m1 = -INFINITY, l0 = 0.f, l1 = 0.f;

    const int w8 = lane & 7;
    const int b3 = (lane >> 3) & 1;
    const int b4 = (lane >> 4) & 1;

    // scale rows for this thread (gmem, L2-resident across 32 bh CTAs)
    const float* scr0 = sf + ((size_t)(qt * kBQ) + (size_t)(wid * 16 + g)) * kS + 2 * t;
    const float* scr1 = scr0 + (size_t)8 * kS;

    for (int kt = 0; kt < kIters; ++kt) {
        cp_wait0();
        __syncthreads();     // tile kt visible; all warps done with other stage
        if (kt + 1 < kIters) issue_tile(kt + 1, (kt + 1) & 1);

        const int st = kt & 1;
        const uint32_t KHI = sb + (uint32_t)st * kBlobB;
        const uint32_t KLO = KHI + kKVTileB;
        const uint32_t VHI = KHI + 2 * kKVTileB;
        const uint32_t VLO = KHI + 3 * kKVTileB;

        // ---- S = Q K^T (3-term) ----
        float sacc[8][4];
        #pragma unroll
        for (int n = 0; n < 8; ++n)
            #pragma unroll
            for (int c = 0; c < 4; ++c) sacc[n][c] = 0.f;

        #pragma unroll
        for (int ks = 0; ks < 8; ++ks) {
            uint32_t bhi[8][2], blo[8][2];
            #pragma unroll
            for (int p = 0; p < 4; ++p) {
                const uint32_t off = (uint32_t)((p * 16 + b4 * 8 + w8) * kKVStrideB
                                                + (ks * 16 + b3 * 8) * 2);
                ldsm_x4(bhi[2*p][0], bhi[2*p][1], bhi[2*p+1][0], bhi[2*p+1][1], KHI + off);
                ldsm_x4(blo[2*p][0], blo[2*p][1], blo[2*p+1][0], blo[2*p+1][1], KLO + off);
            }
            #pragma unroll
            for (int n = 0; n < 8; ++n) {
                mma_bf16(sacc[n], qhi[ks], bhi[n][0], bhi[n][1]);
                mma_bf16(sacc[n], qhi[ks], blo[n][0], blo[n][1]);
                mma_bf16(sacc[n], qlo[ks], bhi[n][0], bhi[n][1]);
            }
        }

        // ---- per-element scale from gmem (L2), then row max ----
        const float* scg0 = scr0 + (size_t)kt * kBK;
        const float* scg1 = scr1 + (size_t)kt * kBK;
        float2 sc0[8], sc1[8];
        #pragma unroll
        for (int n = 0; n < 8; ++n) {
            sc0[n] = *reinterpret_cast<const float2*>(scg0 + n * 8);
            sc1[n] = *reinterpret_cast<const float2*>(scg1 + n * 8);
        }
        float mx0 = -INFINITY, mx1 = -INFINITY;
        #pragma unroll
        for (int n = 0; n < 8; ++n) {
            sacc[n][0] *= sc0[n].x; sacc[n][1] *= sc0[n].y;
            sacc[n][2] *= sc1[n].x; sacc[n][3] *= sc1[n].y;
            mx0 = fmaxf(mx0, fmaxf(sacc[n][0], sacc[n][1]));
            mx1 = fmaxf(mx1, fmaxf(sacc[n][2], sacc[n][3]));
        }
        #pragma unroll
        for (int off = 1; off <= 2; off <<= 1) {
            mx0 = fmaxf(mx0, __shfl_xor_sync(0xffffffffu, mx0, off));
            mx1 = fmaxf(mx1, __shfl_xor_sync(0xffffffffu, mx1, off));
        }
        const float m0n = fmaxf(m0, mx0), m1n = fmaxf(m1, mx1);
        const float a0 = __expf(m0 - m0n), a1 = __expf(m1 - m1n);
        m0 = m0n; m1 = m1n;

        // ---- rescale O (FMA pipe; overlaps tensor) ----
        #pragma unroll
        for (int n = 0; n < 16; ++n) {
            oacc[n][0] *= a0; oacc[n][1] *= a0;
            oacc[n][2] *= a1; oacc[n][3] *= a1;
        }

        // ---- interleaved: per quarter jj -> exp, repack, PV MMAs ----
        float sum0 = 0.f, sum1 = 0.f;
        #pragma unroll
        for (int jj = 0; jj < 4; ++jj) {
            float* sA = sacc[2 * jj];
            float* sB = sacc[2 * jj + 1];
            sA[0] = __expf(sA[0] - m0n); sA[1] = __expf(sA[1] - m0n);
            sA[2] = __expf(sA[2] - m1n); sA[3] = __expf(sA[3] - m1n);
            sB[0] = __expf(sB[0] - m0n); sB[1] = __expf(sB[1] - m0n);
            sB[2] = __expf(sB[2] - m1n); sB[3] = __expf(sB[3] - m1n);
            sum0 += sA[0] + sA[1] + sB[0] + sB[1];
            sum1 += sA[2] + sA[3] + sB[2] + sB[3];

            uint32_t phi[4], plo[4];
            split2(sA[0], sA[1], phi[0], plo[0]);
            split2(sA[2], sA[3], phi[1], plo[1]);
            split2(sB[0], sB[1], phi[2], plo[2]);
            split2(sB[2], sB[3], phi[3], plo[3]);

            #pragma unroll
            for (int pp = 0; pp < 8; ++pp) {
                const uint32_t off = (uint32_t)((jj * 16 + b3 * 8 + w8) * kKVStrideB
                                                + (pp * 16 + b4 * 8) * 2);
                uint32_t vh0, vh1, vh2, vh3, vl0, vl1, vl2, vl3;
                ldsm_x4_t(vh0, vh1, vh2, vh3, VHI + off);
                ldsm_x4_t(vl0, vl1, vl2, vl3, VLO + off);
                mma_bf16(oacc[2*pp],   phi, vh0, vh1);
                mma_bf16(oacc[2*pp],   phi, vl0, vl1);
                mma_bf16(oacc[2*pp],   plo, vh0, vh1);
                mma_bf16(oacc[2*pp+1], phi, vh2, vh3);
                mma_bf16(oacc[2*pp+1], phi, vl2, vl3);
                mma_bf16(oacc[2*pp+1], plo, vh2, vh3);
            }
        }
        #pragma unroll
        for (int off = 1; off <= 2; off <<= 1) {
            sum0 += __shfl_xor_sync(0xffffffffu, sum0, off);
            sum1 += __shfl_xor_sync(0xffffffffu, sum1, off);
        }
        l0 = l0 * a0 + sum0;
        l1 = l1 * a1 + sum1;
    }

    // ---- epilogue ----
    const float dp = decode_scalar(dropout_p);
    const float inv0 = dp / l0, inv1 = dp / l1;
    const size_t row0 = (size_t)bh * kS + (size_t)qt * kBQ + (size_t)(wid * 16 + g);
    float* o0 = out + row0 * kD + 2 * t;
    float* o1 = o0 + (size_t)8 * kD;
    #pragma unroll
    for (int n = 0; n < 16; ++n) {
        *reinterpret_cast<float2*>(o0 + n * 8) = make_float2(oacc[n][0] * inv0, oacc[n][1] * inv0);
        *reinterpret_cast<float2*>(o1 + n * 8) = make_float2(oacc[n][2] * inv1, oacc[n][3] * inv1);
    }
}

extern "C" void kernel_launch(void* const* d_in, const int* in_sizes, int n_in,
                              void* d_out, int out_size) {
    const float* q  = (const float*)d_in[0];
    const float* k  = (const float*)d_in[1];
    const float* v  = (const float*)d_in[2];
    const float* sf = (const float*)d_in[3];
    const void*  dp = d_in[4];
    float* out = (float*)d_out;
    (void)in_sizes; (void)n_in; (void)out_size;

    dim3 cgrid(kIters, 32);
    convert_kv_kernel<<<cgrid, 256>>>(k, v);

    cudaFuncSetAttribute(flash_mma_kernel,
                         cudaFuncAttributeMaxDynamicSharedMemorySize, kSmemBytes);
    dim3 grid(kQTiles, 32);
    flash_mma_kernel<<<grid, kThreads, kSmemBytes>>>(q, sf, dp, out);
}